// round 13
// baseline (speedup 1.0000x reference)
#include <cuda_runtime.h>

#define NN   50000
#define FIN  256
#define HD   128
#define SS   50
#define GG   1000          // NN/SS
#define EMAX 1600000
#define NBLK ((NN + 255) / 256)   // 196

// ---------------- scratch (static device globals; no allocation) ----------------
// RULE (measured R7->R11): device globals may only be STREAMED; every random
// gather must read harness-allocated memory (big pages; device globals thrash TLB).
__device__ __align__(16) int   g_deg[NN];        // .bss zero at load; cleanup re-zeroes
__device__ __align__(16) float g_dinv[NN];
__device__ __align__(16) int   g_rowptr[NN + 1];
__device__ __align__(16) int   g_fill[NN];
__device__ __align__(16) int   g_srcs[EMAX];
__device__ __align__(16) float g_norm[EMAX];
__device__ __align__(16) float g_h1[NN * HD];    // relu(agg(xw)+b1)  (streamed by gemm2)
__device__ __align__(16) float g_ah[NN * HD];    // agg(hw)+b2        (streamed by copy)

// ---------------- CSR build ----------------
// single block, 1024 threads: dinv + full inclusive scan + fill-cursor init
__global__ void k_scan_all() {
    __shared__ int warp_tot[32];
    int tid = threadIdx.x;
    int lane = tid & 31, wid = tid >> 5;
    int carry = 0;

    for (int base = 0; base < NN; base += 1024) {
        int i = base + tid;
        int d = (i < NN) ? g_deg[i] : 0;
        if (i < NN) g_dinv[i] = rsqrtf((float)d + 1.0f);   // +1 self-loop

        int v = d;
        #pragma unroll
        for (int o = 1; o < 32; o <<= 1) {
            int t = __shfl_up_sync(0xffffffffu, v, o);
            if (lane >= o) v += t;
        }
        if (lane == 31) warp_tot[wid] = v;
        __syncthreads();
        if (wid == 0) {
            int w = warp_tot[lane];
            #pragma unroll
            for (int o = 1; o < 32; o <<= 1) {
                int t = __shfl_up_sync(0xffffffffu, w, o);
                if (lane >= o) w += t;
            }
            warp_tot[lane] = w;
        }
        __syncthreads();
        int incl = v + (wid > 0 ? warp_tot[wid - 1] : 0) + carry;
        if (i < NN) {
            g_rowptr[i + 1] = incl;
            g_fill[i] = incl - d;      // exclusive prefix = rowptr[i]
        }
        if (i == 0) g_rowptr[0] = 0;
        carry += warp_tot[31];
        __syncthreads();
    }
}

__global__ void k_fill(const int* __restrict__ src, const int* __restrict__ dst, int Ecnt) {
    int e = blockIdx.x * blockDim.x + threadIdx.x;
    if (e < Ecnt) {
        int s = src[e], d = dst[e];
        int p = atomicAdd(&g_fill[d], 1);
        g_srcs[p] = s;
        g_norm[p] = g_dinv[s] * g_dinv[d];
    }
}

__global__ void k_zero_deg() {           // cleanup for next replay
    int i = blockIdx.x * blockDim.x + threadIdx.x;
    if (i < NN) g_deg[i] = 0;
}

// ---------------- 128-dim aggregation, 4x-unrolled gather ----------------
// one warp per node; O[n] = act( sum norm*T[s] + dinv(n)^2*T[n] + bias )
// T MUST be harness-allocated memory.
__global__ void agg128_k(const float* __restrict__ T, const float* __restrict__ bias,
                         float* __restrict__ O, int relu) {
    int warp = threadIdx.x >> 5, lane = threadIdx.x & 31;
    int node = blockIdx.x * 8 + warp;
    if (node >= NN) return;

    const float4* __restrict__ Tv = (const float4*)T;
    float di = g_dinv[node];
    float w0 = di * di;
    float4 a = Tv[node * 32 + lane];
    float4 acc;
    acc.x = w0 * a.x; acc.y = w0 * a.y; acc.z = w0 * a.z; acc.w = w0 * a.w;

    int b = g_rowptr[node], e = g_rowptr[node + 1];
    int j = b;
    for (; j + 4 <= e; j += 4) {
        int s0 = __ldg(&g_srcs[j + 0]);
        int s1 = __ldg(&g_srcs[j + 1]);
        int s2 = __ldg(&g_srcs[j + 2]);
        int s3 = __ldg(&g_srcs[j + 3]);
        float n0 = __ldg(&g_norm[j + 0]);
        float n1 = __ldg(&g_norm[j + 1]);
        float n2 = __ldg(&g_norm[j + 2]);
        float n3 = __ldg(&g_norm[j + 3]);
        float4 v0 = Tv[s0 * 32 + lane];
        float4 v1 = Tv[s1 * 32 + lane];
        float4 v2 = Tv[s2 * 32 + lane];
        float4 v3 = Tv[s3 * 32 + lane];
        acc.x = fmaf(n0, v0.x, acc.x); acc.y = fmaf(n0, v0.y, acc.y);
        acc.z = fmaf(n0, v0.z, acc.z); acc.w = fmaf(n0, v0.w, acc.w);
        acc.x = fmaf(n1, v1.x, acc.x); acc.y = fmaf(n1, v1.y, acc.y);
        acc.z = fmaf(n1, v1.z, acc.z); acc.w = fmaf(n1, v1.w, acc.w);
        acc.x = fmaf(n2, v2.x, acc.x); acc.y = fmaf(n2, v2.y, acc.y);
        acc.z = fmaf(n2, v2.z, acc.z); acc.w = fmaf(n2, v2.w, acc.w);
        acc.x = fmaf(n3, v3.x, acc.x); acc.y = fmaf(n3, v3.y, acc.y);
        acc.z = fmaf(n3, v3.z, acc.z); acc.w = fmaf(n3, v3.w, acc.w);
    }
    for (; j < e; j++) {
        int s = __ldg(&g_srcs[j]);
        float w = __ldg(&g_norm[j]);
        float4 v = Tv[s * 32 + lane];
        acc.x = fmaf(w, v.x, acc.x);
        acc.y = fmaf(w, v.y, acc.y);
        acc.z = fmaf(w, v.z, acc.z);
        acc.w = fmaf(w, v.w, acc.w);
    }
    float4 bb = ((const float4*)bias)[lane];
    acc.x += bb.x; acc.y += bb.y; acc.z += bb.z; acc.w += bb.w;
    if (relu) {
        acc.x = fmaxf(acc.x, 0.f); acc.y = fmaxf(acc.y, 0.f);
        acc.z = fmaxf(acc.z, 0.f); acc.w = fmaxf(acc.w, 0.f);
    }
    ((float4*)O)[node * 32 + lane] = acc;
}

// ---------------- GEMM 128x128x16: C[M,128] = A[M,K] @ B[K,128] ----------------
// 256 threads; thread (tx=tid&15, ty=tid>>4) computes rows ty*8..+7,
// cols {tx*4..+3} and {tx*4+64..+67} (conflict-free split-column reads).
// Optionally fuses the edge-degree histogram (dst != nullptr).
__global__ void gemm128_k(const float* __restrict__ A, const float* __restrict__ B,
                          float* __restrict__ C, int M, int K,
                          const int* __restrict__ dst, int Ecnt) {
    if (dst) {  // fused edge count (independent side work)
        int nb = gridDim.x;
        int chunk = (Ecnt + nb - 1) / nb;
        int base = blockIdx.x * chunk;
        int end = min(base + chunk, Ecnt);
        for (int e = base + threadIdx.x; e < end; e += blockDim.x)
            atomicAdd(&g_deg[dst[e]], 1);
    }

    __shared__ float As[128][16];
    __shared__ float Bs[16][128];
    int tid = threadIdx.x;
    int tx = tid & 15, ty = tid >> 4;
    int r0 = blockIdx.x * 128;

    float acc[8][8];
    #pragma unroll
    for (int i = 0; i < 8; i++)
        #pragma unroll
        for (int j = 0; j < 8; j++) acc[i][j] = 0.0f;

    for (int kt = 0; kt < K; kt += 16) {
        // As: 128x16 = 512 float4; 2 per thread
        #pragma unroll
        for (int it = 0; it < 2; it++) {
            int l = (tid + it * 256) * 4;
            int row = l >> 4, col = l & 15;
            int gr = r0 + row;
            float4 v = make_float4(0.f, 0.f, 0.f, 0.f);
            if (gr < M) v = *(const float4*)&A[(long)gr * K + kt + col];
            *(float4*)&As[row][col] = v;
        }
        // Bs: 16x128 = 512 float4; 2 per thread
        #pragma unroll
        for (int it = 0; it < 2; it++) {
            int l = (tid + it * 256) * 4;
            int row = l >> 7, col = l & 127;
            *(float4*)&Bs[row][col] = *(const float4*)&B[(kt + row) * 128 + col];
        }
        __syncthreads();

        #pragma unroll
        for (int k = 0; k < 16; k++) {
            float4 b0 = *(float4*)&Bs[k][tx * 4];
            float4 b1 = *(float4*)&Bs[k][tx * 4 + 64];
            #pragma unroll
            for (int i = 0; i < 8; i++) {
                float a = As[ty * 8 + i][k];
                acc[i][0] = fmaf(a, b0.x, acc[i][0]);
                acc[i][1] = fmaf(a, b0.y, acc[i][1]);
                acc[i][2] = fmaf(a, b0.z, acc[i][2]);
                acc[i][3] = fmaf(a, b0.w, acc[i][3]);
                acc[i][4] = fmaf(a, b1.x, acc[i][4]);
                acc[i][5] = fmaf(a, b1.y, acc[i][5]);
                acc[i][6] = fmaf(a, b1.z, acc[i][6]);
                acc[i][7] = fmaf(a, b1.w, acc[i][7]);
            }
        }
        __syncthreads();
    }

    #pragma unroll
    for (int i = 0; i < 8; i++) {
        int r = r0 + ty * 8 + i;
        if (r < M) {
            float4 v0 = make_float4(acc[i][0], acc[i][1], acc[i][2], acc[i][3]);
            float4 v1 = make_float4(acc[i][4], acc[i][5], acc[i][6], acc[i][7]);
            *(float4*)&C[(long)r * 128 + tx * 4] = v0;
            *(float4*)&C[(long)r * 128 + tx * 4 + 64] = v1;
        }
    }
}

// ---------------- copy: emb region <- g_ah (streamed) ----------------
__global__ void k_copy(const float4* __restrict__ src, float4* __restrict__ dst, int n4) {
    int i = blockIdx.x * blockDim.x + threadIdx.x;
    if (i < n4) dst[i] = src[i];
}

// ---------------- pooled head: out[g,j] = sum_k emb[g*6400+k]*Wl[k,j] + bl[j] ----------------
__global__ void pool_k(const float* __restrict__ emb, const float* __restrict__ Wl,
                       const float* __restrict__ bl, float* __restrict__ out) {
    __shared__ float sW[32][128];
    __shared__ float sE[8][33];
    int tid = threadIdx.x;
    int g0 = blockIdx.x * 8;
    int jj = tid & 127, half = tid >> 7;

    float acc[4] = {0.f, 0.f, 0.f, 0.f};

    for (int k0 = 0; k0 < SS * HD; k0 += 32) {
        #pragma unroll
        for (int it = 0; it < 4; it++) {
            int l = (tid + it * 256) * 4;
            int row = l >> 7, col = l & 127;
            *(float4*)&sW[row][col] = *(const float4*)&Wl[(k0 + row) * 128 + col];
        }
        {
            int r = tid >> 5, c = tid & 31;
            sE[r][c] = emb[(g0 + r) * 6400 + k0 + c];
        }
        __syncthreads();

        #pragma unroll
        for (int kk = 0; kk < 32; kk++) {
            float w = sW[kk][jj];
            #pragma unroll
            for (int gg = 0; gg < 4; gg++)
                acc[gg] = fmaf(sE[half * 4 + gg][kk], w, acc[gg]);
        }
        __syncthreads();
    }

    float bv = bl[jj];
    #pragma unroll
    for (int gg = 0; gg < 4; gg++)
        out[(g0 + half * 4 + gg) * 128 + jj] = acc[gg] + bv;
}

// ---------------- launch ----------------
extern "C" void kernel_launch(void* const* d_in, const int* in_sizes, int n_in,
                              void* d_out, int out_size) {
    const float* x  = (const float*)d_in[0];
    const float* W1 = (const float*)d_in[1];
    const float* b1 = (const float*)d_in[2];
    const float* W2 = (const float*)d_in[3];
    const float* b2 = (const float*)d_in[4];
    const float* Wl = (const float*)d_in[5];
    const float* bl = (const float*)d_in[6];
    const int*   ei = (const int*)d_in[7];

    int Ecnt = in_sizes[7] / 2;
    const int* src = ei;
    const int* dst = ei + Ecnt;

    float* out  = (float*)d_out;           // [1000,128]
    float* embR = out + GG * HD;           // [50000,128] harness mem — staging + final emb

    int eb = (Ecnt + 255) / 256;
    int gb = (NN + 127) / 128;             // 391

    // 1: xw = x@W1 -> embR  (+ fused edge-degree histogram; g_deg zero on entry)
    gemm128_k<<<gb, 256>>>(x, W1, embR, NN, FIN, dst, Ecnt);

    // 2-3: CSR build
    k_scan_all<<<1, 1024>>>();
    k_fill<<<eb, 256>>>(src, dst, Ecnt);

    // 4: h1 = relu(agg(xw) + b1) -> g_h1            <-- profiled slot
    agg128_k<<<(NN + 7) / 8, 256>>>(embR, b1, g_h1, 1);

    // 5-6: hw = h1@W2 -> embR ; emb = agg(hw) + b2 -> g_ah
    gemm128_k<<<gb, 256>>>(g_h1, W2, embR, NN, HD, nullptr, 0);
    agg128_k<<<(NN + 7) / 8, 256>>>(embR, b2, g_ah, 0);

    // 7: place final embeddings into output region
    k_copy<<<(NN * HD / 4 + 255) / 256, 256>>>((const float4*)g_ah, (float4*)embR,
                                               NN * HD / 4);

    // 8: pooled head
    pool_k<<<(GG + 7) / 8, 256>>>(embR, Wl, bl, out);

    // 9: cleanup — leave g_deg zeroed for next replay (determinism)
    k_zero_deg<<<NBLK, 256>>>();
}

// round 14
// speedup vs baseline: 1.1000x; 1.1000x over previous
#include <cuda_runtime.h>

#define NN   50000
#define FIN  256
#define HD   128
#define SS   50
#define GG   1000          // NN/SS
#define EMAX 1600000
#define NBLK ((NN + 255) / 256)   // 196

// ---------------- scratch (static device globals; no allocation) ----------------
// RULE (measured R7->R11): device globals may only be STREAMED; every random
// gather must read harness-allocated memory (big pages; device globals thrash TLB).
__device__ __align__(16) int   g_deg[NN];        // .bss zero at load; cleanup re-zeroes
__device__ __align__(16) float g_dinv[NN];
__device__ __align__(16) int   g_rowptr[NN + 1];
__device__ __align__(16) int   g_fill[NN];
__device__ __align__(16) int   g_srcs[EMAX];
__device__ __align__(16) float g_norm[EMAX];
__device__ __align__(16) float g_h1[NN * HD];    // relu(agg(xw)+b1)  (streamed by gemm2)
__device__ __align__(16) float g_ah[NN * HD];    // agg(hw)+b2        (streamed by copy)

// ---------------- CSR build ----------------
__global__ void k_count(const int* __restrict__ dst, int Ecnt) {
    int e = blockIdx.x * blockDim.x + threadIdx.x;
    if (e < Ecnt) atomicAdd(&g_deg[dst[e]], 1);
}

// single block, 1024 threads: dinv + full inclusive scan + fill-cursor init
__global__ void k_scan_all() {
    __shared__ int warp_tot[32];
    int tid = threadIdx.x;
    int lane = tid & 31, wid = tid >> 5;
    int carry = 0;

    for (int base = 0; base < NN; base += 1024) {
        int i = base + tid;
        int d = (i < NN) ? g_deg[i] : 0;
        if (i < NN) g_dinv[i] = rsqrtf((float)d + 1.0f);   // +1 self-loop

        int v = d;
        #pragma unroll
        for (int o = 1; o < 32; o <<= 1) {
            int t = __shfl_up_sync(0xffffffffu, v, o);
            if (lane >= o) v += t;
        }
        if (lane == 31) warp_tot[wid] = v;
        __syncthreads();
        if (wid == 0) {
            int w = warp_tot[lane];
            #pragma unroll
            for (int o = 1; o < 32; o <<= 1) {
                int t = __shfl_up_sync(0xffffffffu, w, o);
                if (lane >= o) w += t;
            }
            warp_tot[lane] = w;
        }
        __syncthreads();
        int incl = v + (wid > 0 ? warp_tot[wid - 1] : 0) + carry;
        if (i < NN) {
            g_rowptr[i + 1] = incl;
            g_fill[i] = incl - d;      // exclusive prefix = rowptr[i]
        }
        if (i == 0) g_rowptr[0] = 0;
        carry += warp_tot[31];
        __syncthreads();
    }
}

__global__ void k_fill(const int* __restrict__ src, const int* __restrict__ dst, int Ecnt) {
    int e = blockIdx.x * blockDim.x + threadIdx.x;
    if (e < Ecnt) {
        int s = src[e], d = dst[e];
        int p = atomicAdd(&g_fill[d], 1);
        g_srcs[p] = s;
        g_norm[p] = g_dinv[s] * g_dinv[d];
    }
}

__global__ void k_zero_deg() {           // cleanup for next replay
    int i = blockIdx.x * blockDim.x + threadIdx.x;
    if (i < NN) g_deg[i] = 0;
}

// ---------------- 128-dim aggregation, 8x-unrolled gather ----------------
// one warp per node; O[n] = act( sum norm*T[s] + dinv(n)^2*T[n] + bias )
// T MUST be harness-allocated memory.
__global__ void agg128_k(const float* __restrict__ T, const float* __restrict__ bias,
                         float* __restrict__ O, int relu) {
    int warp = threadIdx.x >> 5, lane = threadIdx.x & 31;
    int node = blockIdx.x * 8 + warp;
    if (node >= NN) return;

    const float4* __restrict__ Tv = (const float4*)T;
    float di = g_dinv[node];
    float w0 = di * di;
    float4 a = Tv[node * 32 + lane];
    float4 acc;
    acc.x = w0 * a.x; acc.y = w0 * a.y; acc.z = w0 * a.z; acc.w = w0 * a.w;

    int b = g_rowptr[node], e = g_rowptr[node + 1];
    int j = b;
    for (; j + 8 <= e; j += 8) {
        int s0 = __ldg(&g_srcs[j + 0]);
        int s1 = __ldg(&g_srcs[j + 1]);
        int s2 = __ldg(&g_srcs[j + 2]);
        int s3 = __ldg(&g_srcs[j + 3]);
        int s4 = __ldg(&g_srcs[j + 4]);
        int s5 = __ldg(&g_srcs[j + 5]);
        int s6 = __ldg(&g_srcs[j + 6]);
        int s7 = __ldg(&g_srcs[j + 7]);
        float n0 = __ldg(&g_norm[j + 0]);
        float n1 = __ldg(&g_norm[j + 1]);
        float n2 = __ldg(&g_norm[j + 2]);
        float n3 = __ldg(&g_norm[j + 3]);
        float n4 = __ldg(&g_norm[j + 4]);
        float n5 = __ldg(&g_norm[j + 5]);
        float n6 = __ldg(&g_norm[j + 6]);
        float n7 = __ldg(&g_norm[j + 7]);
        float4 v0 = Tv[s0 * 32 + lane];
        float4 v1 = Tv[s1 * 32 + lane];
        float4 v2 = Tv[s2 * 32 + lane];
        float4 v3 = Tv[s3 * 32 + lane];
        float4 v4 = Tv[s4 * 32 + lane];
        float4 v5 = Tv[s5 * 32 + lane];
        float4 v6 = Tv[s6 * 32 + lane];
        float4 v7 = Tv[s7 * 32 + lane];
        acc.x = fmaf(n0, v0.x, acc.x); acc.y = fmaf(n0, v0.y, acc.y);
        acc.z = fmaf(n0, v0.z, acc.z); acc.w = fmaf(n0, v0.w, acc.w);
        acc.x = fmaf(n1, v1.x, acc.x); acc.y = fmaf(n1, v1.y, acc.y);
        acc.z = fmaf(n1, v1.z, acc.z); acc.w = fmaf(n1, v1.w, acc.w);
        acc.x = fmaf(n2, v2.x, acc.x); acc.y = fmaf(n2, v2.y, acc.y);
        acc.z = fmaf(n2, v2.z, acc.z); acc.w = fmaf(n2, v2.w, acc.w);
        acc.x = fmaf(n3, v3.x, acc.x); acc.y = fmaf(n3, v3.y, acc.y);
        acc.z = fmaf(n3, v3.z, acc.z); acc.w = fmaf(n3, v3.w, acc.w);
        acc.x = fmaf(n4, v4.x, acc.x); acc.y = fmaf(n4, v4.y, acc.y);
        acc.z = fmaf(n4, v4.z, acc.z); acc.w = fmaf(n4, v4.w, acc.w);
        acc.x = fmaf(n5, v5.x, acc.x); acc.y = fmaf(n5, v5.y, acc.y);
        acc.z = fmaf(n5, v5.z, acc.z); acc.w = fmaf(n5, v5.w, acc.w);
        acc.x = fmaf(n6, v6.x, acc.x); acc.y = fmaf(n6, v6.y, acc.y);
        acc.z = fmaf(n6, v6.z, acc.z); acc.w = fmaf(n6, v6.w, acc.w);
        acc.x = fmaf(n7, v7.x, acc.x); acc.y = fmaf(n7, v7.y, acc.y);
        acc.z = fmaf(n7, v7.z, acc.z); acc.w = fmaf(n7, v7.w, acc.w);
    }
    for (; j < e; j++) {
        int s = __ldg(&g_srcs[j]);
        float w = __ldg(&g_norm[j]);
        float4 v = Tv[s * 32 + lane];
        acc.x = fmaf(w, v.x, acc.x);
        acc.y = fmaf(w, v.y, acc.y);
        acc.z = fmaf(w, v.z, acc.z);
        acc.w = fmaf(w, v.w, acc.w);
    }
    float4 bb = ((const float4*)bias)[lane];
    acc.x += bb.x; acc.y += bb.y; acc.z += bb.z; acc.w += bb.w;
    if (relu) {
        acc.x = fmaxf(acc.x, 0.f); acc.y = fmaxf(acc.y, 0.f);
        acc.z = fmaxf(acc.z, 0.f); acc.w = fmaxf(acc.w, 0.f);
    }
    ((float4*)O)[node * 32 + lane] = acc;
}

// ---------------- GEMM 128x128x16 (no fusion): C[M,128] = A[M,K] @ B[K,128] ----------------
__global__ void gemm128_k(const float* __restrict__ A, const float* __restrict__ B,
                          float* __restrict__ C, int M, int K) {
    __shared__ float As[128][16];
    __shared__ float Bs[16][128];
    int tid = threadIdx.x;
    int tx = tid & 15, ty = tid >> 4;
    int r0 = blockIdx.x * 128;

    float acc[8][8];
    #pragma unroll
    for (int i = 0; i < 8; i++)
        #pragma unroll
        for (int j = 0; j < 8; j++) acc[i][j] = 0.0f;

    for (int kt = 0; kt < K; kt += 16) {
        #pragma unroll
        for (int it = 0; it < 2; it++) {
            int l = (tid + it * 256) * 4;
            int row = l >> 4, col = l & 15;
            int gr = r0 + row;
            float4 v = make_float4(0.f, 0.f, 0.f, 0.f);
            if (gr < M) v = *(const float4*)&A[(long)gr * K + kt + col];
            *(float4*)&As[row][col] = v;
        }
        #pragma unroll
        for (int it = 0; it < 2; it++) {
            int l = (tid + it * 256) * 4;
            int row = l >> 7, col = l & 127;
            *(float4*)&Bs[row][col] = *(const float4*)&B[(kt + row) * 128 + col];
        }
        __syncthreads();

        #pragma unroll
        for (int k = 0; k < 16; k++) {
            float4 b0 = *(float4*)&Bs[k][tx * 4];
            float4 b1 = *(float4*)&Bs[k][tx * 4 + 64];
            #pragma unroll
            for (int i = 0; i < 8; i++) {
                float a = As[ty * 8 + i][k];
                acc[i][0] = fmaf(a, b0.x, acc[i][0]);
                acc[i][1] = fmaf(a, b0.y, acc[i][1]);
                acc[i][2] = fmaf(a, b0.z, acc[i][2]);
                acc[i][3] = fmaf(a, b0.w, acc[i][3]);
                acc[i][4] = fmaf(a, b1.x, acc[i][4]);
                acc[i][5] = fmaf(a, b1.y, acc[i][5]);
                acc[i][6] = fmaf(a, b1.z, acc[i][6]);
                acc[i][7] = fmaf(a, b1.w, acc[i][7]);
            }
        }
        __syncthreads();
    }

    #pragma unroll
    for (int i = 0; i < 8; i++) {
        int r = r0 + ty * 8 + i;
        if (r < M) {
            float4 v0 = make_float4(acc[i][0], acc[i][1], acc[i][2], acc[i][3]);
            float4 v1 = make_float4(acc[i][4], acc[i][5], acc[i][6], acc[i][7]);
            *(float4*)&C[(long)r * 128 + tx * 4] = v0;
            *(float4*)&C[(long)r * 128 + tx * 4 + 64] = v1;
        }
    }
}

// ---------------- copy: emb region <- g_ah (streamed) ----------------
__global__ void k_copy(const float4* __restrict__ src, float4* __restrict__ dst, int n4) {
    int i = blockIdx.x * blockDim.x + threadIdx.x;
    if (i < n4) dst[i] = src[i];
}

// ---------------- pooled head: out[g,j] = sum_k emb[g*6400+k]*Wl[k,j] + bl[j] ----------------
__global__ void pool_k(const float* __restrict__ emb, const float* __restrict__ Wl,
                       const float* __restrict__ bl, float* __restrict__ out) {
    __shared__ float sW[32][128];
    __shared__ float sE[8][33];
    int tid = threadIdx.x;
    int g0 = blockIdx.x * 8;
    int jj = tid & 127, half = tid >> 7;

    float acc[4] = {0.f, 0.f, 0.f, 0.f};

    for (int k0 = 0; k0 < SS * HD; k0 += 32) {
        #pragma unroll
        for (int it = 0; it < 4; it++) {
            int l = (tid + it * 256) * 4;
            int row = l >> 7, col = l & 127;
            *(float4*)&sW[row][col] = *(const float4*)&Wl[(k0 + row) * 128 + col];
        }
        {
            int r = tid >> 5, c = tid & 31;
            sE[r][c] = emb[(g0 + r) * 6400 + k0 + c];
        }
        __syncthreads();

        #pragma unroll
        for (int kk = 0; kk < 32; kk++) {
            float w = sW[kk][jj];
            #pragma unroll
            for (int gg = 0; gg < 4; gg++)
                acc[gg] = fmaf(sE[half * 4 + gg][kk], w, acc[gg]);
        }
        __syncthreads();
    }

    float bv = bl[jj];
    #pragma unroll
    for (int gg = 0; gg < 4; gg++)
        out[(g0 + half * 4 + gg) * 128 + jj] = acc[gg] + bv;
}

// ---------------- launch ----------------
extern "C" void kernel_launch(void* const* d_in, const int* in_sizes, int n_in,
                              void* d_out, int out_size) {
    const float* x  = (const float*)d_in[0];
    const float* W1 = (const float*)d_in[1];
    const float* b1 = (const float*)d_in[2];
    const float* W2 = (const float*)d_in[3];
    const float* b2 = (const float*)d_in[4];
    const float* Wl = (const float*)d_in[5];
    const float* bl = (const float*)d_in[6];
    const int*   ei = (const int*)d_in[7];

    int Ecnt = in_sizes[7] / 2;
    const int* src = ei;
    const int* dst = ei + Ecnt;

    float* out  = (float*)d_out;           // [1000,128]
    float* embR = out + GG * HD;           // [50000,128] harness mem — staging + final emb

    int eb = (Ecnt + 255) / 256;
    int gb = (NN + 127) / 128;             // 391

    // CSR build (g_deg zero on entry)
    k_count<<<eb, 256>>>(dst, Ecnt);                                 // 1
    k_scan_all<<<1, 1024>>>();                                       // 2
    k_fill<<<eb, 256>>>(src, dst, Ecnt);                             // 3

    // 4: xw = x@W1 -> embR                            <-- profiled slot (tile decision)
    gemm128_k<<<gb, 256>>>(x, W1, embR, NN, FIN);

    // 5: h1 = relu(agg(xw) + b1) -> g_h1
    agg128_k<<<(NN + 7) / 8, 256>>>(embR, b1, g_h1, 1);

    // 6-7: hw = h1@W2 -> embR ; emb = agg(hw) + b2 -> g_ah
    gemm128_k<<<gb, 256>>>(g_h1, W2, embR, NN, HD);
    agg128_k<<<(NN + 7) / 8, 256>>>(embR, b2, g_ah, 0);

    // 8: place final embeddings into output region
    k_copy<<<(NN * HD / 4 + 255) / 256, 256>>>((const float4*)g_ah, (float4*)embR,
                                               NN * HD / 4);

    // 9: pooled head
    pool_k<<<(GG + 7) / 8, 256>>>(embR, Wl, bl, out);

    // 10: cleanup — leave g_deg zeroed for next replay (determinism)
    k_zero_deg<<<NBLK, 256>>>();
}